// round 9
// baseline (speedup 1.0000x reference)
#include <cuda_runtime.h>
#include <cuda_bf16.h>
#include <cstdint>

// Problem constants
#define NUM_CHIPS 4
#define SEQ 1024
#define HIDDEN 2048
#define TOP_K 4
#define N_EXPERTS 32
#define MAX_TOK 1024
#define META_LEN 8
#define N_PER_CHIP (SEQ * TOP_K)           // 4096
#define N_TOTAL (NUM_CHIPS * N_PER_CHIP)   // 16384 assignments
#define N_CHUNKS (N_TOTAL / 32)            // 512 warp-chunks, chip-major
#define TOTAL_SLOTS (N_EXPERTS * MAX_TOK)  // 32768
#define BUF_ELEMS ((size_t)TOTAL_SLOTS * HIDDEN)
#define META_OFF  BUF_ELEMS
#define CNT_OFF   (BUF_ELEMS + (size_t)TOTAL_SLOTS * META_LEN)

#define PLAN_BLOCKS 16          // blocks 0..15 plan chunks; block 16 emits totals

// Scratch (no allocations allowed)
__device__ int g_src[TOTAL_SLOTS];   // slot -> assignment id (first cnt_e per expert valid)
__device__ int g_cnt[N_EXPERTS];     // per-expert totals

// ---------------------------------------------------------------------------
// Planning: 17 blocks x 1024 threads. NO cross-block sync: each block
// redundantly histograms the assignments that precede its region.
//   slot(a) = e*1024 + hist_before_block[e] + within_block_prefix[e] + rank
// Block 16 computes the full histogram -> g_cnt + output counters.
// ---------------------------------------------------------------------------
__global__ void __launch_bounds__(1024) plan_kernel(const int* __restrict__ idx,
                                                    float* __restrict__ out) {
    __shared__ int s_hist[N_EXPERTS];          // histogram of preceding region
    __shared__ int s_cnt[32][N_EXPERTS];       // per-warp per-expert counts (this block)
    __shared__ int s_pref[N_EXPERTS][32];      // exclusive warp prefix per expert

    const int warp = threadIdx.x >> 5;
    const int lane = threadIdx.x & 31;
    const unsigned lt = (1u << lane) - 1u;
    const int b = blockIdx.x;

    if (threadIdx.x < N_EXPERTS) s_hist[threadIdx.x] = 0;
    s_cnt[warp][lane] = 0;

    if (b == PLAN_BLOCKS) {
        // Totals block: histogram ALL 512 chunks.
        __syncthreads();
        for (int ch = warp; ch < N_CHUNKS; ch += 32) {
            const int e = __ldg(&idx[ch * 32 + lane]);
            const unsigned m = __match_any_sync(0xFFFFFFFFu, e);
            if ((m & lt) == 0) atomicAdd(&s_hist[e], __popc(m));
        }
        __syncthreads();
        if (threadIdx.x < N_EXPERTS) {
            g_cnt[threadIdx.x] = s_hist[threadIdx.x];
            out[CNT_OFF + threadIdx.x] = (float)s_hist[threadIdx.x];
        }
        return;
    }

    // --- Own chunk: rank + count (warp w owns chunk b*32+w) ---
    const int a = (b * 32 + warp) * 32 + lane;
    const int e = __ldg(&idx[a]);
    const unsigned m = __match_any_sync(0xFFFFFFFFu, e);
    const int rk = __popc(m & lt);
    __syncwarp();
    if (rk == 0) s_cnt[warp][e] = __popc(m);   // distinct e per leader lane: no conflict

    // --- Redundant histogram of preceding region [0, b*32) chunks ---
    for (int ch = warp; ch < b * 32; ch += 32) {
        const int pe = __ldg(&idx[ch * 32 + lane]);
        const unsigned pm = __match_any_sync(0xFFFFFFFFu, pe);
        if ((pm & lt) == 0) atomicAdd(&s_hist[pe], __popc(pm));
    }
    __syncthreads();

    // --- Warp ex scans expert ex's 32 per-warp counts (exclusive) ---
    {
        const int ex = warp;
        const int c = s_cnt[lane][ex];
        int s = c;
#pragma unroll
        for (int d = 1; d < 32; d <<= 1) {
            int t = __shfl_up_sync(0xFFFFFFFFu, s, d);
            if (lane >= d) s += t;
        }
        s_pref[ex][lane] = s - c;              // bank-conflict-free (row-major by lane)
    }
    __syncthreads();

    // --- Emit inverse map ---
    const int slot = e * MAX_TOK + s_hist[e] + s_pref[e][warp] + rk;
    g_src[slot] = a;
}

// ---------------------------------------------------------------------------
// Gather: one block per slot; copy token row (or zeros) + 8 meta words.
// Proven fast path: plain float4 stores, 256 threads.
// ---------------------------------------------------------------------------
__global__ void __launch_bounds__(256) gather_kernel(const float* __restrict__ x,
                                                     const float* __restrict__ w,
                                                     float* __restrict__ out) {
    const int slot = blockIdx.x;
    const int e    = slot >> 10;
    const int si   = slot & (MAX_TOK - 1);
    const int t    = threadIdx.x;
    float4* dst = reinterpret_cast<float4*>(out + (size_t)slot * HIDDEN);
    float4* md  = reinterpret_cast<float4*>(out + META_OFF + (size_t)slot * META_LEN);

    if (si < g_cnt[e]) {
        const int a   = g_src[slot];
        const int c   = a >> 12;
        const int n   = a & (N_PER_CHIP - 1);
        const int tok = n >> 2;
        const float4* src =
            reinterpret_cast<const float4*>(x + ((size_t)c * SEQ + tok) * HIDDEN);
        float4 v0 = src[t];
        float4 v1 = src[t + 256];
        dst[t]       = v0;
        dst[t + 256] = v1;
        if (t == 0) {
            __nv_bfloat16 hb = __float2bfloat16(w[a]);
            unsigned short bits = __bfloat16_as_ushort(hb);
            md[0] = make_float4((float)c, (float)tok, (float)(n & 3), (float)e);
            md[1] = make_float4((float)bits, 0.f, 0.f, 0.f);
        }
    } else {
        const float4 z = make_float4(0.f, 0.f, 0.f, 0.f);
        dst[t]       = z;
        dst[t + 256] = z;
        if (t == 0) {
            const float4 neg = make_float4(-1.f, -1.f, -1.f, -1.f);
            md[0] = neg;
            md[1] = neg;
        }
    }
}

// ---------------------------------------------------------------------------
extern "C" void kernel_launch(void* const* d_in, const int* in_sizes, int n_in,
                              void* d_out, int out_size) {
    const float* x   = (const float*)d_in[0];   // [4,1024,2048] f32
    const float* wts = (const float*)d_in[1];   // [4,1024,4]    f32
    const int*   ind = (const int*)  d_in[2];   // [4,1024,4]    i32
    float* out = (float*)d_out;

    plan_kernel<<<PLAN_BLOCKS + 1, 1024>>>(ind, out);
    gather_kernel<<<TOTAL_SLOTS, 256>>>(x, wts, out);
}

// round 10
// speedup vs baseline: 1.2272x; 1.2272x over previous
#include <cuda_runtime.h>
#include <cuda_bf16.h>
#include <cstdint>

// Problem constants
#define NUM_CHIPS 4
#define SEQ 1024
#define HIDDEN 2048
#define TOP_K 4
#define N_EXPERTS 32
#define MAX_TOK 1024
#define META_LEN 8
#define N_PER_CHIP (SEQ * TOP_K)           // 4096
#define N_TOTAL (NUM_CHIPS * N_PER_CHIP)   // 16384 assignments
#define N_CHUNKS (N_TOTAL / 32)            // 512 warp-chunks, chip-major
#define TOTAL_SLOTS (N_EXPERTS * MAX_TOK)  // 32768
#define BUF_ELEMS ((size_t)TOTAL_SLOTS * HIDDEN)
#define META_OFF  BUF_ELEMS
#define CNT_OFF   (BUF_ELEMS + (size_t)TOTAL_SLOTS * META_LEN)

#define PLAN_BLOCKS 16          // blocks 0..15 plan chunks; block 16 emits totals
#define SLOTS_PER_BLOCK 2
#define GATHER_THREADS 512

// Scratch (no allocations allowed)
__device__ int g_src[TOTAL_SLOTS];   // slot -> assignment id (first cnt_e per expert valid)
__device__ int g_cnt[N_EXPERTS];     // per-expert totals

// ---------------------------------------------------------------------------
// Planning: 17 blocks x 1024 threads, NO cross-block sync. Each block
// redundantly histograms the assignments preceding its region:
//   slot(a) = e*1024 + hist_before_block[e] + within_block_prefix[e] + rank
// Block 16 computes the full histogram -> g_cnt + output counters.
// Ends with a PDL trigger so the gather grid can pre-launch.
// ---------------------------------------------------------------------------
__global__ void __launch_bounds__(1024) plan_kernel(const int* __restrict__ idx,
                                                    float* __restrict__ out) {
    __shared__ int s_hist[N_EXPERTS];          // histogram of preceding region
    __shared__ int s_cnt[32][N_EXPERTS];       // per-warp per-expert counts (this block)
    __shared__ int s_pref[N_EXPERTS][32];      // exclusive warp prefix per expert

    const int warp = threadIdx.x >> 5;
    const int lane = threadIdx.x & 31;
    const unsigned lt = (1u << lane) - 1u;
    const int b = blockIdx.x;

    if (threadIdx.x < N_EXPERTS) s_hist[threadIdx.x] = 0;
    s_cnt[warp][lane] = 0;

    if (b == PLAN_BLOCKS) {
        __syncthreads();
        for (int ch = warp; ch < N_CHUNKS; ch += 32) {
            const int e = __ldg(&idx[ch * 32 + lane]);
            const unsigned m = __match_any_sync(0xFFFFFFFFu, e);
            if ((m & lt) == 0) atomicAdd(&s_hist[e], __popc(m));
        }
        __syncthreads();
        if (threadIdx.x < N_EXPERTS) {
            g_cnt[threadIdx.x] = s_hist[threadIdx.x];
            out[CNT_OFF + threadIdx.x] = (float)s_hist[threadIdx.x];
        }
        __threadfence();
        cudaTriggerProgrammaticLaunchCompletion();
        return;
    }

    // Own chunk: rank + count (warp w owns chunk b*32+w).
    const int a = (b * 32 + warp) * 32 + lane;
    const int e = __ldg(&idx[a]);
    const unsigned m = __match_any_sync(0xFFFFFFFFu, e);
    const int rk = __popc(m & lt);
    __syncwarp();
    if (rk == 0) s_cnt[warp][e] = __popc(m);   // leaders hold distinct e: no conflict

    // Redundant histogram of preceding region [0, b*32) chunks.
    for (int ch = warp; ch < b * 32; ch += 32) {
        const int pe = __ldg(&idx[ch * 32 + lane]);
        const unsigned pm = __match_any_sync(0xFFFFFFFFu, pe);
        if ((pm & lt) == 0) atomicAdd(&s_hist[pe], __popc(pm));
    }
    __syncthreads();

    // Warp ex scans expert ex's 32 per-warp counts (exclusive).
    {
        const int ex = warp;
        const int c = s_cnt[lane][ex];
        int s = c;
#pragma unroll
        for (int d = 1; d < 32; d <<= 1) {
            int t = __shfl_up_sync(0xFFFFFFFFu, s, d);
            if (lane >= d) s += t;
        }
        s_pref[ex][lane] = s - c;
    }
    __syncthreads();

    // Emit inverse map, then PDL trigger.
    const int slot = e * MAX_TOK + s_hist[e] + s_pref[e][warp] + rk;
    g_src[slot] = a;
    __threadfence();
    cudaTriggerProgrammaticLaunchCompletion();
}

// ---------------------------------------------------------------------------
// Gather: 2 slots per 512-thread block; 256-thread group per slot copies the
// 2048-float row (or zeros) + 8 meta words. PDL: blocks pre-launch, then wait
// on the plan grid before reading g_src / g_cnt.
// ---------------------------------------------------------------------------
__global__ void __launch_bounds__(GATHER_THREADS) gather_kernel(
    const float* __restrict__ x, const float* __restrict__ w,
    float* __restrict__ out)
{
    cudaGridDependencySynchronize();

    const int grp  = threadIdx.x >> 8;                    // 0 or 1
    const int t    = threadIdx.x & 255;
    const int slot = blockIdx.x * SLOTS_PER_BLOCK + grp;
    const int e    = slot >> 10;
    const int si   = slot & (MAX_TOK - 1);
    float4* dst = reinterpret_cast<float4*>(out + (size_t)slot * HIDDEN);
    float4* md  = reinterpret_cast<float4*>(out + META_OFF + (size_t)slot * META_LEN);

    if (si < g_cnt[e]) {
        const int a   = g_src[slot];
        const int c   = a >> 12;
        const int n   = a & (N_PER_CHIP - 1);
        const int tok = n >> 2;
        const float4* src =
            reinterpret_cast<const float4*>(x + ((size_t)c * SEQ + tok) * HIDDEN);
        float4 v0 = src[t];
        float4 v1 = src[t + 256];
        dst[t]       = v0;
        dst[t + 256] = v1;
        if (t == 0) {
            __nv_bfloat16 hb = __float2bfloat16(w[a]);
            unsigned short bits = __bfloat16_as_ushort(hb);
            md[0] = make_float4((float)c, (float)tok, (float)(n & 3), (float)e);
            md[1] = make_float4((float)bits, 0.f, 0.f, 0.f);
        }
    } else {
        const float4 z = make_float4(0.f, 0.f, 0.f, 0.f);
        dst[t]       = z;
        dst[t + 256] = z;
        if (t == 0) {
            const float4 neg = make_float4(-1.f, -1.f, -1.f, -1.f);
            md[0] = neg;
            md[1] = neg;
        }
    }
}

// ---------------------------------------------------------------------------
extern "C" void kernel_launch(void* const* d_in, const int* in_sizes, int n_in,
                              void* d_out, int out_size) {
    const float* x   = (const float*)d_in[0];   // [4,1024,2048] f32
    const float* wts = (const float*)d_in[1];   // [4,1024,4]    f32
    const int*   ind = (const int*)  d_in[2];   // [4,1024,4]    i32
    float* out = (float*)d_out;

    plan_kernel<<<PLAN_BLOCKS + 1, 1024>>>(ind, out);

    // Gather with programmatic dependent launch: pre-spawn while plan drains.
    cudaLaunchAttribute attrs[1];
    attrs[0].id = cudaLaunchAttributeProgrammaticStreamSerialization;
    attrs[0].val.programmaticStreamSerializationAllowed = 1;

    cudaLaunchConfig_t cfg = {};
    cfg.gridDim  = dim3(TOTAL_SLOTS / SLOTS_PER_BLOCK, 1, 1);
    cfg.blockDim = dim3(GATHER_THREADS, 1, 1);
    cfg.dynamicSmemBytes = 0;
    cfg.stream = 0;                 // legacy default stream (same as <<<>>>)
    cfg.attrs = attrs;
    cfg.numAttrs = 1;

    cudaLaunchKernelEx(&cfg, gather_kernel, x, wts, out);
}